// round 12
// baseline (speedup 1.0000x reference)
#include <cuda_runtime.h>

// Problem constants
#define B_  8192
#define T_  336
#define F_  8
#define H_  20
#define NPAIR (B_ / 2)           // 4096
#define L_  3
#define ITER (T_ + 2 * (L_ - 1)) // 340

typedef unsigned long long u64;

// ---- packed f32x2 helpers (sm_103a) ----
__device__ __forceinline__ u64 pk(float lo, float hi) {
    u64 r; asm("mov.b64 %0, {%1, %2};" : "=l"(r) : "f"(lo), "f"(hi)); return r;
}
__device__ __forceinline__ float2 upk(u64 v) {
    float2 f; asm("mov.b64 {%0, %1}, %2;" : "=f"(f.x), "=f"(f.y) : "l"(v)); return f;
}
__device__ __forceinline__ u64 ffma2(u64 a, u64 b, u64 c) {
    u64 d; asm("fma.rn.f32x2 %0, %1, %2, %3;" : "=l"(d) : "l"(a), "l"(b), "l"(c)); return d;
}
__device__ __forceinline__ u64 fmul2(u64 a, u64 b) {
    u64 d; asm("mul.rn.f32x2 %0, %1, %2;" : "=l"(d) : "l"(a), "l"(b)); return d;
}
__device__ __forceinline__ float sig1(float x) {
    return __fdividef(1.f, 1.f + __expf(-x));
}
__device__ __forceinline__ float tanhap(float x) {   // MUFU.TANH (output path only)
    float y; asm("tanh.approx.f32 %0, %1;" : "=f"(y) : "f"(x)); return y;
}

// ============================================================================
// Fused 3-layer LSTM + FC head, single barrier per wavefront iteration.
// Block = 1 element pair, 128 threads (120 work + 8 mirrors), 5 blocks/SM.
// Thread (l, r): r = u*2 + half; half0 owns rows {u, u+40} (i, g);
// half1 owns {u+20, u+60} (f, o). i*g ships to half1 via 64-bit shfl_xor(1).
// W_hh k-packed in registers (critical dot); W_ih k-packed in SHARED
// (bubble dot, latency-tolerant) to cut regs ~128 -> ~95 for 5 blocks/SM.
// Wavefront skew 2: layer l at iter j computes t = j - 2l.
// ============================================================================
__global__ __launch_bounds__(128, 5)
void lstm_fused3(
    const float* __restrict__ x,
    const float* __restrict__ W_ih0, const float* __restrict__ W_hh0,
    const float* __restrict__ b_ih0, const float* __restrict__ b_hh0,
    const float* __restrict__ W_ih1, const float* __restrict__ W_hh1,
    const float* __restrict__ b_ih1, const float* __restrict__ b_hh1,
    const float* __restrict__ W_ih2, const float* __restrict__ W_hh2,
    const float* __restrict__ b_ih2, const float* __restrict__ b_hh2,
    const float* __restrict__ fc1_w, const float* __restrict__ fc1_b,
    const float* __restrict__ fc2_w, const float* __restrict__ fc2_b,
    float* __restrict__ out_final)
{
    // h ring: [layer][slot][elem][unit]  (written at iter j into slot j&3)
    __shared__ __align__(16) float s_h[L_][4][2][H_];
    // L0 input ring, padded to 20 feats (8..19 stay zero)
    __shared__ __align__(16) float s_x0[4][2][H_];
    // W_ih tile: [layer][r][0..9 = row0 k-pairs | 10..19 = row1 k-pairs]
    __shared__ __align__(16) u64 s_wih[L_][40][2 * (H_ / 2)];
    __shared__ float s_fc[2][H_];

    const int tid  = threadIdx.x;
    int l = tid / 40; if (l > 2) l = 2;          // tids 120..127 mirror layer 2
    const int r    = (tid - l * 40) % 40;        // 0..39
    const int u    = r >> 1;
    const int half = r & 1;
    const size_t pair = blockIdx.x;

    const int row0 = u + 20 * half;              // i or f
    const int row1 = u + 40 + 20 * half;         // g or o

    const float* __restrict__ Wih = (l == 0) ? W_ih0 : (l == 1) ? W_ih1 : W_ih2;
    const float* __restrict__ Whh = (l == 0) ? W_hh0 : (l == 1) ? W_hh1 : W_hh2;
    const float* __restrict__ bih = (l == 0) ? b_ih0 : (l == 1) ? b_ih1 : b_ih2;
    const float* __restrict__ bhh = (l == 0) ? b_hh0 : (l == 1) ? b_hh1 : b_hh2;
    const int INl = (l == 0) ? F_ : H_;

    // W_hh k-packed in regs (critical path): w[q] = {W[row][2q], W[row][2q+1]}
    u64 whhA[H_ / 2], whhB[H_ / 2];
    #pragma unroll
    for (int q = 0; q < H_ / 2; ++q) {
        whhA[q] = pk(__ldg(&Whh[row0 * H_ + 2 * q]), __ldg(&Whh[row0 * H_ + 2 * q + 1]));
        whhB[q] = pk(__ldg(&Whh[row1 * H_ + 2 * q]), __ldg(&Whh[row1 * H_ + 2 * q + 1]));
    }
    // W_ih k-packed into SHARED (mirrors write duplicates of identical data)
    #pragma unroll
    for (int q = 0; q < H_ / 2; ++q) {
        float a0 = (2 * q     < INl) ? __ldg(&Wih[row0 * INl + 2 * q])     : 0.f;
        float a1 = (2 * q + 1 < INl) ? __ldg(&Wih[row0 * INl + 2 * q + 1]) : 0.f;
        float b0 = (2 * q     < INl) ? __ldg(&Wih[row1 * INl + 2 * q])     : 0.f;
        float b1 = (2 * q + 1 < INl) ? __ldg(&Wih[row1 * INl + 2 * q + 1]) : 0.f;
        s_wih[l][r][q]              = pk(a0, a1);
        s_wih[l][r][H_ / 2 + q]     = pk(b0, b1);
    }
    const float bias0 = __ldg(&bih[row0]) + __ldg(&bhh[row0]);
    const float bias1 = __ldg(&bih[row1]) + __ldg(&bhh[row1]);
    // row0 always sigmoid; row1 tanh for half0 (g), sigmoid for half1 (o)
    const float sc1 = half ? -1.f : -2.f;
    const float am1 = half ?  1.f :  2.f;
    const float bm1 = half ?  0.f : -1.f;

    // L0 staging role: l==0 && r<16 -> (elx = r&1, feat = r>>1)
    const int elx = r & 1, feat = r >> 1;
    const float* __restrict__ myin = x + (size_t)(2 * pair + elx) * T_ * F_ + feat;

    // ---- zero-init smem rings (s_wih written above by all work threads) ----
    for (int i = tid; i < L_ * 4 * 2 * H_; i += 128) ((float*)s_h)[i] = 0.f;
    for (int i = tid; i < 4 * 2 * H_; i += 128)      ((float*)s_x0)[i] = 0.f;
    __syncthreads();

    // stage x[0], x[1]; prefetch x[2]
    float xr = 0.f;
    if (l == 0 && r < 16) {
        s_x0[0][elx][feat] = myin[0];
        s_x0[1][elx][feat] = myin[(size_t)1 * F_];
        xr = myin[(size_t)2 * F_];
    }
    __syncthreads();

    // K-packed dot, weights in REGISTERS (critical W_hh dot)
    #define KDOT(vbase, wA, wB, o00, o01, o10, o11) do {                       \
        const ulonglong2* _v0 = (const ulonglong2*)(vbase);                    \
        const ulonglong2* _v1 = (const ulonglong2*)((vbase) + H_);             \
        u64 _a00 = 0ULL, _a01 = 0ULL, _a10 = 0ULL, _a11 = 0ULL;                \
        _Pragma("unroll")                                                      \
        for (int q = 0; q < 5; ++q) {                                          \
            ulonglong2 _p0 = _v0[q], _p1 = _v1[q];                             \
            _a00 = ffma2(_p0.x, wA[2 * q],     _a00);                          \
            _a00 = ffma2(_p0.y, wA[2 * q + 1], _a00);                          \
            _a01 = ffma2(_p1.x, wA[2 * q],     _a01);                          \
            _a01 = ffma2(_p1.y, wA[2 * q + 1], _a01);                          \
            _a10 = ffma2(_p0.x, wB[2 * q],     _a10);                          \
            _a10 = ffma2(_p0.y, wB[2 * q + 1], _a10);                          \
            _a11 = ffma2(_p1.x, wB[2 * q + 1 - 1], _a11);                      \
            _a11 = ffma2(_p1.y, wB[2 * q + 1], _a11);                          \
        }                                                                      \
        float2 _f;                                                             \
        _f = upk(_a00); o00 = _f.x + _f.y;                                     \
        _f = upk(_a01); o01 = _f.x + _f.y;                                     \
        _f = upk(_a10); o10 = _f.x + _f.y;                                     \
        _f = upk(_a11); o11 = _f.x + _f.y;                                     \
    } while (0)

    // K-packed dot, weights in SHARED (bubble W_ih dot)
    #define KDOT_S(vbase, wbase, o00, o01, o10, o11) do {                      \
        const ulonglong2* _v0 = (const ulonglong2*)(vbase);                    \
        const ulonglong2* _v1 = (const ulonglong2*)((vbase) + H_);             \
        const ulonglong2* _w0 = (const ulonglong2*)(wbase);                    \
        const ulonglong2* _w1 = (const ulonglong2*)((wbase) + H_ / 2);         \
        u64 _a00 = 0ULL, _a01 = 0ULL, _a10 = 0ULL, _a11 = 0ULL;                \
        _Pragma("unroll")                                                      \
        for (int q = 0; q < 5; ++q) {                                          \
            ulonglong2 _p0 = _v0[q], _p1 = _v1[q];                             \
            ulonglong2 _q0 = _w0[q], _q1 = _w1[q];                             \
            _a00 = ffma2(_p0.x, _q0.x, _a00);                                  \
            _a00 = ffma2(_p0.y, _q0.y, _a00);                                  \
            _a01 = ffma2(_p1.x, _q0.x, _a01);                                  \
            _a01 = ffma2(_p1.y, _q0.y, _a01);                                  \
            _a10 = ffma2(_p0.x, _q1.x, _a10);                                  \
            _a10 = ffma2(_p0.y, _q1.y, _a10);                                  \
            _a11 = ffma2(_p1.x, _q1.x, _a11);                                  \
            _a11 = ffma2(_p1.y, _q1.y, _a11);                                  \
        }                                                                      \
        float2 _f;                                                             \
        _f = upk(_a00); o00 = _f.x + _f.y;                                     \
        _f = upk(_a01); o01 = _f.x + _f.y;                                     \
        _f = upk(_a10); o10 = _f.x + _f.y;                                     \
        _f = upk(_a11); o11 = _f.x + _f.y;                                     \
    } while (0)

    // prologue xpart for j=0 (layer0: x slot0; l>0: zeroed h slot 2)
    float xp00, xp01, xp10, xp11;
    {
        const float* vb = (l == 0) ? &s_x0[0][0][0] : &s_h[l - 1][2][0][0];
        KDOT_S(vb, &s_wih[l][r][0], xp00, xp01, xp10, xp11);
        xp00 += bias0; xp01 += bias0; xp10 += bias1; xp11 += bias1;
    }

    u64 c2 = 0ULL;

    for (int j = 0; j < ITER; ++j) {
        const int tl = j - 2 * l;
        const bool active = (tl >= 0) && (tl < T_);

        // stage x[j+2]; prefetch x[j+3]
        if (l == 0 && r < 16) {
            if (j + 2 < T_) s_x0[(j + 2) & 3][elx][feat] = xr;
            const int tn = (j + 3 < T_) ? j + 3 : T_ - 1;
            xr = myin[(size_t)tn * F_];
        }

        // critical: W_hh · h[t-1]  (ring slot (j+3)&3 == (j-1)&3)
        float s00, s01, s10, s11;
        KDOT(&s_h[l][(j + 3) & 3][0][0], whhA, whhB, s00, s01, s10, s11);
        const float p00 = xp00 + s00, p01 = xp01 + s01;
        const float p10 = xp10 + s10, p11 = xp11 + s11;

        // activations (row0 sigmoid; row1 tanh/sigmoid by half) — exact path
        const u64 Y0 = pk(sig1(p00), sig1(p01));
        const u64 Y1 = pk(fmaf(am1, __fdividef(1.f, 1.f + __expf(sc1 * p10)), bm1),
                          fmaf(am1, __fdividef(1.f, 1.f + __expf(sc1 * p11)), bm1));

        // half0 ships i*g to half1 (adjacent lane)
        const u64 P = fmul2(Y0, Y1);
        const u64 Precv = __shfl_xor_sync(0xFFFFFFFFu, P, 1);

        if (active && half) {   // half1 holds f (Y0) and o (Y1)
            c2 = ffma2(Y0, c2, Precv);
            float2 cf = upk(c2);
            float t0 = tanhap(cf.x);          // output path: MUFU.TANH
            float t1 = tanhap(cf.y);
            float2 hf = upk(fmul2(Y1, pk(t0, t1)));
            s_h[l][j & 3][0][u] = hf.x;
            s_h[l][j & 3][1][u] = hf.y;
        }

        // bubble: xpart for iter j+1 (inputs synced at previous barrier)
        {
            const float* vb = (l == 0)
                ? &s_x0[(j + 1) & 3][0][0]
                : &s_h[l - 1][(j + 3) & 3][0][0];
            KDOT_S(vb, &s_wih[l][r][0], xp00, xp01, xp10, xp11);
            xp00 += bias0; xp01 += bias0; xp10 += bias1; xp11 += bias1;
        }

        __syncthreads();
    }

    // ---- FC head on layer 2's final h (ring slot (ITER-1)&3 = 3) ----
    if (l == 2) {   // 40 work threads (+8 benign mirrors): elem = half, unit = u
        const float* hfin = &s_h[2][(ITER - 1) & 3][half][0];
        float d = __ldg(&fc1_b[u]);
        #pragma unroll
        for (int k = 0; k < H_; ++k)
            d = fmaf(hfin[k], __ldg(&fc1_w[u * H_ + k]), d);
        d = fmaxf(d, 0.f);
        s_fc[half][u] = d * __ldg(&fc2_w[u]);
    }
    __syncthreads();
    if (tid == 80 || tid == 81) {   // layer-2 r=0 (half0) and r=1 (half1)
        const int po = tid - 80;
        float p = __ldg(&fc2_b[0]);
        #pragma unroll
        for (int k = 0; k < H_; ++k) p += s_fc[po][k];
        out_final[2 * pair + po] = p;
    }
}

extern "C" void kernel_launch(void* const* d_in, const int* in_sizes, int n_in,
                              void* d_out, int out_size) {
    const float* x     = (const float*)d_in[0];
    const float* Wih0  = (const float*)d_in[1];
    const float* Whh0  = (const float*)d_in[2];
    const float* bih0  = (const float*)d_in[3];
    const float* bhh0  = (const float*)d_in[4];
    const float* Wih1  = (const float*)d_in[5];
    const float* Whh1  = (const float*)d_in[6];
    const float* bih1  = (const float*)d_in[7];
    const float* bhh1  = (const float*)d_in[8];
    const float* Wih2  = (const float*)d_in[9];
    const float* Whh2  = (const float*)d_in[10];
    const float* bih2  = (const float*)d_in[11];
    const float* bhh2  = (const float*)d_in[12];
    const float* fc1w  = (const float*)d_in[13];
    const float* fc1b  = (const float*)d_in[14];
    const float* fc2w  = (const float*)d_in[15];
    const float* fc2b  = (const float*)d_in[16];
    float* out = (float*)d_out;

    lstm_fused3<<<NPAIR, 128>>>(
        x,
        Wih0, Whh0, bih0, bhh0,
        Wih1, Whh1, bih1, bhh1,
        Wih2, Whh2, bih2, bhh2,
        fc1w, fc1b, fc2w, fc2b,
        out);
}

// round 13
// speedup vs baseline: 1.6840x; 1.6840x over previous
#include <cuda_runtime.h>

// Problem constants
#define B_  8192
#define T_  336
#define F_  8
#define H_  20
#define NPAIR (B_ / 2)           // 4096
#define L_  3
#define ITER (T_ + 2 * (L_ - 1)) // 340

typedef unsigned long long u64;

// ---- packed f32x2 helpers (sm_103a) ----
__device__ __forceinline__ u64 pk(float lo, float hi) {
    u64 r; asm("mov.b64 %0, {%1, %2};" : "=l"(r) : "f"(lo), "f"(hi)); return r;
}
__device__ __forceinline__ float2 upk(u64 v) {
    float2 f; asm("mov.b64 {%0, %1}, %2;" : "=f"(f.x), "=f"(f.y) : "l"(v)); return f;
}
__device__ __forceinline__ u64 ffma2(u64 a, u64 b, u64 c) {
    u64 d; asm("fma.rn.f32x2 %0, %1, %2, %3;" : "=l"(d) : "l"(a), "l"(b), "l"(c)); return d;
}
__device__ __forceinline__ u64 fmul2(u64 a, u64 b) {
    u64 d; asm("mul.rn.f32x2 %0, %1, %2;" : "=l"(d) : "l"(a), "l"(b)); return d;
}
__device__ __forceinline__ float tanhap(float x) {   // MUFU.TANH
    float y; asm("tanh.approx.f32 %0, %1;" : "=f"(y) : "f"(x)); return y;
}
__device__ __forceinline__ float sigt(float x) {     // sigmoid via MUFU.TANH
    return fmaf(0.5f, tanhap(0.5f * x), 0.5f);
}

// ============================================================================
// Fused 3-layer LSTM + FC head, single barrier per wavefront iteration.
// Block = 1 element pair, 128 threads (120 work + 8 redundant mirrors).
// Work thread (l, r): r = u*2 + half. half0 owns gate rows {u, u+40} (i, g);
// half1 owns {u+20, u+60} (f, o). Gate product i*g crosses to half1 via one
// 64-bit shfl_xor(1); half1 updates the cell and writes h. K-packed weights
// ALL IN REGISTERS (R12 showed smem weights saturate L1). All activations
// via MUFU.TANH (R12 empirically validated accuracy on the recurrence path).
// Wavefront skew 2: layer l at iter j computes t = j - 2l.
// ============================================================================
__global__ __launch_bounds__(128, 4)
void lstm_fused3(
    const float* __restrict__ x,
    const float* __restrict__ W_ih0, const float* __restrict__ W_hh0,
    const float* __restrict__ b_ih0, const float* __restrict__ b_hh0,
    const float* __restrict__ W_ih1, const float* __restrict__ W_hh1,
    const float* __restrict__ b_ih1, const float* __restrict__ b_hh1,
    const float* __restrict__ W_ih2, const float* __restrict__ W_hh2,
    const float* __restrict__ b_ih2, const float* __restrict__ b_hh2,
    const float* __restrict__ fc1_w, const float* __restrict__ fc1_b,
    const float* __restrict__ fc2_w, const float* __restrict__ fc2_b,
    float* __restrict__ out_final)
{
    // h ring: [layer][slot][elem][unit]  (written at iter j into slot j&3)
    __shared__ __align__(16) float s_h[L_][4][2][H_];
    // L0 input ring, padded to 20 feats (8..19 stay zero)
    __shared__ __align__(16) float s_x0[4][2][H_];
    __shared__ float s_fc[2][H_];

    const int tid  = threadIdx.x;
    int l = tid / 40; if (l > 2) l = 2;          // tids 120..127 mirror layer 2
    const int r    = (tid - l * 40) % 40;        // 0..39
    const int u    = r >> 1;
    const int half = r & 1;
    const size_t pair = blockIdx.x;

    const int row0 = u + 20 * half;              // i or f
    const int row1 = u + 40 + 20 * half;         // g or o

    const float* __restrict__ Wih = (l == 0) ? W_ih0 : (l == 1) ? W_ih1 : W_ih2;
    const float* __restrict__ Whh = (l == 0) ? W_hh0 : (l == 1) ? W_hh1 : W_hh2;
    const float* __restrict__ bih = (l == 0) ? b_ih0 : (l == 1) ? b_ih1 : b_ih2;
    const float* __restrict__ bhh = (l == 0) ? b_hh0 : (l == 1) ? b_hh1 : b_hh2;
    const int INl = (l == 0) ? F_ : H_;

    // k-packed weights: w[q] = {W[row][2q], W[row][2q+1]}; W_ih zero-padded to 20
    u64 whhA[H_ / 2], whhB[H_ / 2], wihA[H_ / 2], wihB[H_ / 2];
    #pragma unroll
    for (int q = 0; q < H_ / 2; ++q) {
        whhA[q] = pk(__ldg(&Whh[row0 * H_ + 2 * q]), __ldg(&Whh[row0 * H_ + 2 * q + 1]));
        whhB[q] = pk(__ldg(&Whh[row1 * H_ + 2 * q]), __ldg(&Whh[row1 * H_ + 2 * q + 1]));
        float a0 = (2 * q     < INl) ? __ldg(&Wih[row0 * INl + 2 * q])     : 0.f;
        float a1 = (2 * q + 1 < INl) ? __ldg(&Wih[row0 * INl + 2 * q + 1]) : 0.f;
        float b0 = (2 * q     < INl) ? __ldg(&Wih[row1 * INl + 2 * q])     : 0.f;
        float b1 = (2 * q + 1 < INl) ? __ldg(&Wih[row1 * INl + 2 * q + 1]) : 0.f;
        wihA[q] = pk(a0, a1);
        wihB[q] = pk(b0, b1);
    }
    const float bias0 = __ldg(&bih[row0]) + __ldg(&bhh[row0]);
    const float bias1 = __ldg(&bih[row1]) + __ldg(&bhh[row1]);
    // row0 always sigmoid; row1 tanh for half0 (g), sigmoid for half1 (o)
    // act(x) = fma(am, tanh(ks * x), bm): sigmoid -> am=.5,bm=.5,ks=.5 ; tanh -> 1,0,1
    const float ks1 = half ? 0.5f : 1.f;
    const float am1 = half ? 0.5f : 1.f;
    const float bm1 = half ? 0.5f : 0.f;

    // L0 staging role: l==0 && r<16 -> (elx = r&1, feat = r>>1)
    const int elx = r & 1, feat = r >> 1;
    const float* __restrict__ myin = x + (size_t)(2 * pair + elx) * T_ * F_ + feat;

    // ---- zero-init all smem rings ----
    for (int i = tid; i < L_ * 4 * 2 * H_; i += 128) ((float*)s_h)[i] = 0.f;
    for (int i = tid; i < 4 * 2 * H_; i += 128)      ((float*)s_x0)[i] = 0.f;
    __syncthreads();

    // stage x[0], x[1]; prefetch x[2]
    float xr = 0.f;
    if (l == 0 && r < 16) {
        s_x0[0][elx][feat] = myin[0];
        s_x0[1][elx][feat] = myin[(size_t)1 * F_];
        xr = myin[(size_t)2 * F_];
    }
    __syncthreads();

    // K-packed dot over a [2][20]-float vector: 4 independent 10-FFMA2 chains
    #define KDOT(vbase, wA, wB, o00, o01, o10, o11) do {                       \
        const ulonglong2* _v0 = (const ulonglong2*)(vbase);                    \
        const ulonglong2* _v1 = (const ulonglong2*)((vbase) + H_);             \
        u64 _a00 = 0ULL, _a01 = 0ULL, _a10 = 0ULL, _a11 = 0ULL;                \
        _Pragma("unroll")                                                      \
        for (int q = 0; q < 5; ++q) {                                          \
            ulonglong2 _p0 = _v0[q], _p1 = _v1[q];                             \
            _a00 = ffma2(_p0.x, wA[2 * q],     _a00);                          \
            _a00 = ffma2(_p0.y, wA[2 * q + 1], _a00);                          \
            _a01 = ffma2(_p1.x, wA[2 * q],     _a01);                          \
            _a01 = ffma2(_p1.y, wA[2 * q + 1], _a01);                          \
            _a10 = ffma2(_p0.x, wB[2 * q],     _a10);                          \
            _a10 = ffma2(_p0.y, wB[2 * q + 1], _a10);                          \
            _a11 = ffma2(_p1.x, wB[2 * q],     _a11);                          \
            _a11 = ffma2(_p1.y, wB[2 * q + 1], _a11);                          \
        }                                                                      \
        float2 _f;                                                             \
        _f = upk(_a00); o00 = _f.x + _f.y;                                     \
        _f = upk(_a01); o01 = _f.x + _f.y;                                     \
        _f = upk(_a10); o10 = _f.x + _f.y;                                     \
        _f = upk(_a11); o11 = _f.x + _f.y;                                     \
    } while (0)

    // prologue xpart for j=0 (layer0: x slot0; l>0: zeroed h slot 2)
    float xp00, xp01, xp10, xp11;
    {
        const float* vb = (l == 0) ? &s_x0[0][0][0] : &s_h[l - 1][2][0][0];
        KDOT(vb, wihA, wihB, xp00, xp01, xp10, xp11);
        xp00 += bias0; xp01 += bias0; xp10 += bias1; xp11 += bias1;
    }

    u64 c2 = 0ULL;

    for (int j = 0; j < ITER; ++j) {
        const int tl = j - 2 * l;
        const bool active = (tl >= 0) && (tl < T_);

        // stage x[j+2]; prefetch x[j+3]
        if (l == 0 && r < 16) {
            if (j + 2 < T_) s_x0[(j + 2) & 3][elx][feat] = xr;
            const int tn = (j + 3 < T_) ? j + 3 : T_ - 1;
            xr = myin[(size_t)tn * F_];
        }

        // critical: W_hh · h[t-1]  (ring slot (j+3)&3 == (j-1)&3)
        float s00, s01, s10, s11;
        KDOT(&s_h[l][(j + 3) & 3][0][0], whhA, whhB, s00, s01, s10, s11);
        const float p00 = xp00 + s00, p01 = xp01 + s01;
        const float p10 = xp10 + s10, p11 = xp11 + s11;

        // activations — all MUFU.TANH
        const u64 Y0 = pk(sigt(p00), sigt(p01));
        const u64 Y1 = pk(fmaf(am1, tanhap(ks1 * p10), bm1),
                          fmaf(am1, tanhap(ks1 * p11), bm1));

        // half0 ships i*g to half1 (adjacent lane)
        const u64 P = fmul2(Y0, Y1);
        const u64 Precv = __shfl_xor_sync(0xFFFFFFFFu, P, 1);

        if (active && half) {   // half1 holds f (Y0) and o (Y1)
            c2 = ffma2(Y0, c2, Precv);
            float2 cf = upk(c2);
            float t0 = tanhap(cf.x);
            float t1 = tanhap(cf.y);
            float2 hf = upk(fmul2(Y1, pk(t0, t1)));
            s_h[l][j & 3][0][u] = hf.x;
            s_h[l][j & 3][1][u] = hf.y;
        }

        // bubble: xpart for iter j+1 (inputs synced at previous barrier)
        {
            const float* vb = (l == 0)
                ? &s_x0[(j + 1) & 3][0][0]
                : &s_h[l - 1][(j + 3) & 3][0][0];
            KDOT(vb, wihA, wihB, xp00, xp01, xp10, xp11);
            xp00 += bias0; xp01 += bias0; xp10 += bias1; xp11 += bias1;
        }

        __syncthreads();
    }

    // ---- FC head on layer 2's final h (ring slot (ITER-1)&3 = 3) ----
    if (l == 2) {   // 40 work threads (+8 benign mirrors): elem = half, unit = u
        const float* hfin = &s_h[2][(ITER - 1) & 3][half][0];
        float d = __ldg(&fc1_b[u]);
        #pragma unroll
        for (int k = 0; k < H_; ++k)
            d = fmaf(hfin[k], __ldg(&fc1_w[u * H_ + k]), d);
        d = fmaxf(d, 0.f);
        s_fc[half][u] = d * __ldg(&fc2_w[u]);
    }
    __syncthreads();
    if (tid == 80 || tid == 81) {   // layer-2 r=0 (half0) and r=1 (half1)
        const int po = tid - 80;
        float p = __ldg(&fc2_b[0]);
        #pragma unroll
        for (int k = 0; k < H_; ++k) p += s_fc[po][k];
        out_final[2 * pair + po] = p;
    }
}

extern "C" void kernel_launch(void* const* d_in, const int* in_sizes, int n_in,
                              void* d_out, int out_size) {
    const float* x     = (const float*)d_in[0];
    const float* Wih0  = (const float*)d_in[1];
    const float* Whh0  = (const float*)d_in[2];
    const float* bih0  = (const float*)d_in[3];
    const float* bhh0  = (const float*)d_in[4];
    const float* Wih1  = (const float*)d_in[5];
    const float* Whh1  = (const float*)d_in[6];
    const float* bih1  = (const float*)d_in[7];
    const float* bhh1  = (const float*)d_in[8];
    const float* Wih2  = (const float*)d_in[9];
    const float* Whh2  = (const float*)d_in[10];
    const float* bih2  = (const float*)d_in[11];
    const float* bhh2  = (const float*)d_in[12];
    const float* fc1w  = (const float*)d_in[13];
    const float* fc1b  = (const float*)d_in[14];
    const float* fc2w  = (const float*)d_in[15];
    const float* fc2b  = (const float*)d_in[16];
    float* out = (float*)d_out;

    lstm_fused3<<<NPAIR, 128>>>(
        x,
        Wih0, Whh0, bih0, bhh0,
        Wih1, Whh1, bih1, bhh1,
        Wih2, Whh2, bih2, bhh2,
        fc1w, fc1b, fc2w, fc2b,
        out);
}

// round 14
// speedup vs baseline: 1.7634x; 1.0472x over previous
#include <cuda_runtime.h>

// Problem constants
#define B_  8192
#define T_  336
#define F_  8
#define H_  20
#define L_  3
#define ITER (T_ + 2 * (L_ - 1)) // 340

typedef unsigned long long u64;

// ---- packed f32x2 helpers (sm_103a) ----
__device__ __forceinline__ u64 pk(float lo, float hi) {
    u64 r; asm("mov.b64 %0, {%1, %2};" : "=l"(r) : "f"(lo), "f"(hi)); return r;
}
__device__ __forceinline__ float2 upk(u64 v) {
    float2 f; asm("mov.b64 {%0, %1}, %2;" : "=f"(f.x), "=f"(f.y) : "l"(v)); return f;
}
__device__ __forceinline__ u64 ffma2(u64 a, u64 b, u64 c) {
    u64 d; asm("fma.rn.f32x2 %0, %1, %2, %3;" : "=l"(d) : "l"(a), "l"(b), "l"(c)); return d;
}
__device__ __forceinline__ u64 fmul2(u64 a, u64 b) {
    u64 d; asm("mul.rn.f32x2 %0, %1, %2;" : "=l"(d) : "l"(a), "l"(b)); return d;
}
__device__ __forceinline__ float tanhap(float x) {   // MUFU.TANH
    float y; asm("tanh.approx.f32 %0, %1;" : "=f"(y) : "f"(x)); return y;
}

// ============================================================================
// Fused 3-layer LSTM + FC head. Block = 4 elements (2 packed pairs),
// 128 threads (120 work + 8 mirrors). Weight registers amortized over 2 pairs.
// Thread (l, r): r = u*2 + half; half0 owns rows {u,u+40} (i,g), half1 owns
// {u+20,u+60} (f,o); i*g ships to half1 via 64-bit shfl_xor(1), per pair.
// All activations MUFU.TANH (validated R12/R13). Single barrier per iter.
// Wavefront skew 2: layer l at iter j computes t = j - 2l.
// ============================================================================
__global__ __launch_bounds__(128, 3)
void lstm_fused3(
    const float* __restrict__ x,
    const float* __restrict__ W_ih0, const float* __restrict__ W_hh0,
    const float* __restrict__ b_ih0, const float* __restrict__ b_hh0,
    const float* __restrict__ W_ih1, const float* __restrict__ W_hh1,
    const float* __restrict__ b_ih1, const float* __restrict__ b_hh1,
    const float* __restrict__ W_ih2, const float* __restrict__ W_hh2,
    const float* __restrict__ b_ih2, const float* __restrict__ b_hh2,
    const float* __restrict__ fc1_w, const float* __restrict__ fc1_b,
    const float* __restrict__ fc2_w, const float* __restrict__ fc2_b,
    float* __restrict__ out_final)
{
    // h ring: [layer][slot][elem0..3][unit]
    __shared__ __align__(16) float s_h[L_][4][4][H_];
    // L0 input ring, padded to 20 feats (8..19 stay zero)
    __shared__ __align__(16) float s_x0[4][4][H_];
    __shared__ float s_fc[4][H_];

    const int tid  = threadIdx.x;
    int l = tid / 40; if (l > 2) l = 2;          // tids 120..127 mirror layer 2
    const int r    = (tid - l * 40) % 40;        // 0..39
    const int u    = r >> 1;
    const int half = r & 1;
    const size_t blk = blockIdx.x;               // 4 elems: 4*blk .. 4*blk+3

    const int row0 = u + 20 * half;              // i or f
    const int row1 = u + 40 + 20 * half;         // g or o

    const float* __restrict__ Wih = (l == 0) ? W_ih0 : (l == 1) ? W_ih1 : W_ih2;
    const float* __restrict__ Whh = (l == 0) ? W_hh0 : (l == 1) ? W_hh1 : W_hh2;
    const float* __restrict__ bih = (l == 0) ? b_ih0 : (l == 1) ? b_ih1 : b_ih2;
    const float* __restrict__ bhh = (l == 0) ? b_hh0 : (l == 1) ? b_hh1 : b_hh2;
    const int INl = (l == 0) ? F_ : H_;

    // k-packed weights: w[q] = {W[row][2q], W[row][2q+1]}; W_ih zero-padded to 20
    u64 whhA[H_ / 2], whhB[H_ / 2], wihA[H_ / 2], wihB[H_ / 2];
    #pragma unroll
    for (int q = 0; q < H_ / 2; ++q) {
        whhA[q] = pk(__ldg(&Whh[row0 * H_ + 2 * q]), __ldg(&Whh[row0 * H_ + 2 * q + 1]));
        whhB[q] = pk(__ldg(&Whh[row1 * H_ + 2 * q]), __ldg(&Whh[row1 * H_ + 2 * q + 1]));
        float a0 = (2 * q     < INl) ? __ldg(&Wih[row0 * INl + 2 * q])     : 0.f;
        float a1 = (2 * q + 1 < INl) ? __ldg(&Wih[row0 * INl + 2 * q + 1]) : 0.f;
        float b0 = (2 * q     < INl) ? __ldg(&Wih[row1 * INl + 2 * q])     : 0.f;
        float b1 = (2 * q + 1 < INl) ? __ldg(&Wih[row1 * INl + 2 * q + 1]) : 0.f;
        wihA[q] = pk(a0, a1);
        wihB[q] = pk(b0, b1);
    }
    const float bias0 = __ldg(&bih[row0]) + __ldg(&bhh[row0]);
    const float bias1 = __ldg(&bih[row1]) + __ldg(&bhh[row1]);
    // row0 always sigmoid (= .5*tanh(.5x)+.5); row1 tanh (half0) / sigmoid (half1)
    const float ks1 = half ? 0.5f : 1.f;
    const u64 am2 = half ? pk(0.5f, 0.5f) : pk(1.f, 1.f);
    const u64 bm2 = half ? pk(0.5f, 0.5f) : pk(0.f, 0.f);
    const u64 h2c = pk(0.5f, 0.5f);

    // L0 staging role: l==0 && r<32 -> (selem = r&3, feat = r>>2)
    const int selem = r & 3, feat = r >> 2;
    const float* __restrict__ myin = x + (size_t)(4 * blk + selem) * T_ * F_ + feat;

    // ---- zero-init smem rings ----
    for (int i = tid; i < L_ * 4 * 4 * H_; i += 128) ((float*)s_h)[i] = 0.f;
    for (int i = tid; i < 4 * 4 * H_; i += 128)      ((float*)s_x0)[i] = 0.f;
    __syncthreads();

    // stage x[0], x[1]; prefetch x[2]
    float xr = 0.f;
    if (l == 0 && r < 32) {
        s_x0[0][selem][feat] = myin[0];
        s_x0[1][selem][feat] = myin[(size_t)1 * F_];
        xr = myin[(size_t)2 * F_];
    }
    __syncthreads();

    // K-packed dot over a [2][20]-float vector: 4 independent 10-FFMA2 chains
    #define KDOT(vbase, wA, wB, o00, o01, o10, o11) do {                       \
        const ulonglong2* _v0 = (const ulonglong2*)(vbase);                    \
        const ulonglong2* _v1 = (const ulonglong2*)((vbase) + H_);             \
        u64 _a00 = 0ULL, _a01 = 0ULL, _a10 = 0ULL, _a11 = 0ULL;                \
        _Pragma("unroll")                                                      \
        for (int q = 0; q < 5; ++q) {                                          \
            ulonglong2 _p0 = _v0[q], _p1 = _v1[q];                             \
            _a00 = ffma2(_p0.x, wA[2 * q],     _a00);                          \
            _a00 = ffma2(_p0.y, wA[2 * q + 1], _a00);                          \
            _a01 = ffma2(_p1.x, wA[2 * q],     _a01);                          \
            _a01 = ffma2(_p1.y, wA[2 * q + 1], _a01);                          \
            _a10 = ffma2(_p0.x, wB[2 * q],     _a10);                          \
            _a10 = ffma2(_p0.y, wB[2 * q + 1], _a10);                          \
            _a11 = ffma2(_p1.x, wB[2 * q],     _a11);                          \
            _a11 = ffma2(_p1.y, wB[2 * q + 1], _a11);                          \
        }                                                                      \
        float2 _f;                                                             \
        _f = upk(_a00); o00 = _f.x + _f.y;                                     \
        _f = upk(_a01); o01 = _f.x + _f.y;                                     \
        _f = upk(_a10); o10 = _f.x + _f.y;                                     \
        _f = upk(_a11); o11 = _f.x + _f.y;                                     \
    } while (0)

    // carried x-part per pair: [pair][rowA e0, rowA e1, rowB e0, rowB e1]
    float xp[2][4];
    #pragma unroll
    for (int P = 0; P < 2; ++P) {
        const float* vb = (l == 0) ? &s_x0[0][2 * P][0] : &s_h[l - 1][2][2 * P][0];
        KDOT(vb, wihA, wihB, xp[P][0], xp[P][1], xp[P][2], xp[P][3]);
        xp[P][0] += bias0; xp[P][1] += bias0; xp[P][2] += bias1; xp[P][3] += bias1;
    }

    u64 c2[2] = {0ULL, 0ULL};

    for (int j = 0; j < ITER; ++j) {
        const int tl = j - 2 * l;
        const bool active = (tl >= 0) && (tl < T_);

        // stage x[j+2]; prefetch x[j+3]
        if (l == 0 && r < 32) {
            if (j + 2 < T_) s_x0[(j + 2) & 3][selem][feat] = xr;
            const int tn = (j + 3 < T_) ? j + 3 : T_ - 1;
            xr = myin[(size_t)tn * F_];
        }

        // critical: W_hh · h[t-1] for both pairs (ring slot (j+3)&3 == (j-1)&3)
        float pre[2][4];
        #pragma unroll
        for (int P = 0; P < 2; ++P) {
            float s0, s1, s2, s3;
            KDOT(&s_h[l][(j + 3) & 3][2 * P][0], whhA, whhB, s0, s1, s2, s3);
            pre[P][0] = xp[P][0] + s0; pre[P][1] = xp[P][1] + s1;
            pre[P][2] = xp[P][2] + s2; pre[P][3] = xp[P][3] + s3;
        }

        // activations — all MUFU.TANH, packed epilogues
        u64 Y0[2], Y1[2], Pp[2];
        #pragma unroll
        for (int P = 0; P < 2; ++P) {
            Y0[P] = ffma2(pk(tanhap(0.5f * pre[P][0]), tanhap(0.5f * pre[P][1])), h2c, h2c);
            Y1[P] = ffma2(pk(tanhap(ks1 * pre[P][2]),  tanhap(ks1 * pre[P][3])),  am2, bm2);
            Pp[P] = fmul2(Y0[P], Y1[P]);
        }
        const u64 Pr0 = __shfl_xor_sync(0xFFFFFFFFu, Pp[0], 1);
        const u64 Pr1 = __shfl_xor_sync(0xFFFFFFFFu, Pp[1], 1);

        if (active && half) {   // half1 holds f (Y0) and o (Y1)
            #pragma unroll
            for (int P = 0; P < 2; ++P) {
                c2[P] = ffma2(Y0[P], c2[P], P ? Pr1 : Pr0);
                float2 cf = upk(c2[P]);
                float2 hf = upk(fmul2(Y1[P], pk(tanhap(cf.x), tanhap(cf.y))));
                s_h[l][j & 3][2 * P][u]     = hf.x;
                s_h[l][j & 3][2 * P + 1][u] = hf.y;
            }
        }

        // bubble: x-part for iter j+1 (inputs synced at previous barrier)
        #pragma unroll
        for (int P = 0; P < 2; ++P) {
            const float* vb = (l == 0)
                ? &s_x0[(j + 1) & 3][2 * P][0]
                : &s_h[l - 1][(j + 3) & 3][2 * P][0];
            float s0, s1, s2, s3;
            KDOT(vb, wihA, wihB, s0, s1, s2, s3);
            xp[P][0] = bias0 + s0; xp[P][1] = bias0 + s1;
            xp[P][2] = bias1 + s2; xp[P][3] = bias1 + s3;
        }

        __syncthreads();
    }

    // ---- FC head on layer 2's final h (ring slot (ITER-1)&3 = 3) ----
    if (l == 2) {   // thread (u, half) -> elems {2*half, 2*half+1}, unit u
        #pragma unroll
        for (int em2 = 0; em2 < 2; ++em2) {
            const int em = 2 * half + em2;
            const float* hfin = &s_h[2][(ITER - 1) & 3][em][0];
            float d = __ldg(&fc1_b[u]);
            #pragma unroll
            for (int k = 0; k < H_; ++k)
                d = fmaf(hfin[k], __ldg(&fc1_w[u * H_ + k]), d);
            d = fmaxf(d, 0.f);
            s_fc[em][u] = d * __ldg(&fc2_w[u]);
        }
    }
    __syncthreads();
    if (tid >= 80 && tid < 84) {   // layer-2 r = 0..3: one output elem each
        const int po = tid - 80;
        float p = __ldg(&fc2_b[0]);
        #pragma unroll
        for (int k = 0; k < H_; ++k) p += s_fc[po][k];
        out_final[4 * blk + po] = p;
    }
}

extern "C" void kernel_launch(void* const* d_in, const int* in_sizes, int n_in,
                              void* d_out, int out_size) {
    const float* x     = (const float*)d_in[0];
    const float* Wih0  = (const float*)d_in[1];
    const float* Whh0  = (const float*)d_in[2];
    const float* bih0  = (const float*)d_in[3];
    const float* bhh0  = (const float*)d_in[4];
    const float* Wih1  = (const float*)d_in[5];
    const float* Whh1  = (const float*)d_in[6];
    const float* bih1  = (const float*)d_in[7];
    const float* bhh1  = (const float*)d_in[8];
    const float* Wih2  = (const float*)d_in[9];
    const float* Whh2  = (const float*)d_in[10];
    const float* bih2  = (const float*)d_in[11];
    const float* bhh2  = (const float*)d_in[12];
    const float* fc1w  = (const float*)d_in[13];
    const float* fc1b  = (const float*)d_in[14];
    const float* fc2w  = (const float*)d_in[15];
    const float* fc2b  = (const float*)d_in[16];
    float* out = (float*)d_out;

    lstm_fused3<<<B_ / 4, 128>>>(
        x,
        Wih0, Whh0, bih0, bhh0,
        Wih1, Whh1, bih1, bhh1,
        Wih2, Whh2, bih2, bhh2,
        fc1w, fc1b, fc2w, fc2b,
        out);
}